// round 16
// baseline (speedup 1.0000x reference)
#include <cuda_runtime.h>
#include <cuda_bf16.h>
#include <cuda_fp16.h>
#include <math.h>
#include <stdint.h>

#define BB 4
#define SS 1024
#define CC 576
#define NH 8
#define DK 72
#define LL 4
#define PD 192
#define FF 2304
#define MM (BB*SS)
#define QKN (2*CC)           // 1152

#define BM 128
#define STAGES 3

// ---------------- scratch (device globals; no runtime allocation) ----------------
__device__ __align__(16) float g_xf[MM*CC];

__device__ __align__(16) __half g_hh[MM*CC];                  // ln out (fp16)
__device__ __align__(16) __half g_qkh[(long)MM*QKN];          // q,k (fp16)
__device__ __align__(16) __half g_vf[MM*CC];                  // v (fp16)
__device__ __align__(16) __half g_af[MM*CC];                  // attention out (fp16)
__device__ __align__(16) __half g_ffn[(long)MM*FF];           // gelu out (fp16)

// ones vector for flash row-sum column (dim 72 = 1.0, 73..79 = 0)
__device__ __align__(16) unsigned short g_ones[8] = {0x3C00u, 0, 0, 0, 0, 0, 0, 0};

// wq,wk transposed [N][K] fp16 hi/lo (2-term path)
#define WLAYER  (2*CC*CC)
__device__ __align__(16) __half g_wth[(long)LL*WLAYER];
__device__ __align__(16) __half g_wtl[(long)LL*WLAYER];
// wo/wv/w1/w2 transposed single fp16 (1-term path)
#define WO2_OFF 0
#define WV2_OFF (CC*CC)
#define W12_OFF (2*CC*CC)
#define W22_OFF (2*CC*CC + CC*FF)
#define W2LAYER (2*CC*CC + 2*CC*FF)
__device__ __align__(16) __half g_fwh[(long)LL*W2LAYER];

// ================= PTX helpers =================
__device__ __forceinline__ uint32_t smem_u32(const void* p) {
    uint32_t a;
    asm("{ .reg .u64 t; cvta.to.shared.u64 t, %1; cvt.u32.u64 %0, t; }" : "=r"(a) : "l"(p));
    return a;
}
__device__ __forceinline__ void cpasync16(uint32_t dst, const void* src, int sz) {
    asm volatile("cp.async.cg.shared.global [%0], [%1], 16, %2;"
                 :: "r"(dst), "l"(src), "r"(sz) : "memory");
}
#define CP_COMMIT() asm volatile("cp.async.commit_group;" ::: "memory")
#define CP_WAIT(n)  asm volatile("cp.async.wait_group %0;" :: "n"(n) : "memory")

__device__ __forceinline__ void ldsm4(uint32_t (&r)[4], uint32_t addr) {
    asm volatile("ldmatrix.sync.aligned.m8n8.x4.shared.b16 {%0,%1,%2,%3}, [%4];"
        : "=r"(r[0]), "=r"(r[1]), "=r"(r[2]), "=r"(r[3]) : "r"(addr));
}
__device__ __forceinline__ void ldsm4t(uint32_t (&r)[4], uint32_t addr) {
    asm volatile("ldmatrix.sync.aligned.m8n8.x4.trans.shared.b16 {%0,%1,%2,%3}, [%4];"
        : "=r"(r[0]), "=r"(r[1]), "=r"(r[2]), "=r"(r[3]) : "r"(addr));
}
__device__ __forceinline__ void mma16816(float (&d)[4], const uint32_t (&a)[4],
                                         uint32_t b0, uint32_t b1) {
    asm volatile("mma.sync.aligned.m16n8k16.row.col.f32.f16.f16.f32 "
        "{%0,%1,%2,%3}, {%4,%5,%6,%7}, {%8,%9}, {%0,%1,%2,%3};"
        : "+f"(d[0]), "+f"(d[1]), "+f"(d[2]), "+f"(d[3])
        : "r"(a[0]), "r"(a[1]), "r"(a[2]), "r"(a[3]), "r"(b0), "r"(b1));
}
__device__ __forceinline__ uint32_t swz64(uint32_t o) { return o ^ ((o >> 3) & 0x30); }
__device__ __forceinline__ uint32_t swz128(uint32_t o) { return o ^ ((o >> 3) & 0x70); }
__device__ __forceinline__ uint32_t ex2h2(float a, float b) {
    __half2 h = __floats2half2_rn(a, b);
    uint32_t in = *(uint32_t*)&h, out;
    asm("ex2.approx.f16x2 %0, %1;" : "=r"(out) : "r"(in));
    return out;
}
__device__ __forceinline__ float ex2f(float x) {
    float r;
    asm("ex2.approx.f32 %0, %1;" : "=f"(r) : "f"(x));
    return r;
}

// ---------------- shift + positional embedding ----------------
__global__ void shiftpos_kernel(const float* __restrict__ x,
                                const float* __restrict__ p0,
                                const float* __restrict__ p1,
                                const float* __restrict__ p2,
                                float* __restrict__ xf) {
    long idx = (long)blockIdx.x * blockDim.x + threadIdx.x;
    if (idx >= (long)MM*CC) return;
    int c = (int)(idx % CC);
    long bs = idx / CC;
    int s = (int)(bs % SS);
    float v = (s == 0) ? 0.f : x[idx - CC];
    int t = s >> 8, hh = (s >> 4) & 15, w = s & 15;
    float p;
    if (c < PD)          p = p0[t * PD + c];
    else if (c < 2 * PD) p = p1[hh * PD + (c - PD)];
    else                 p = p2[w * PD + (c - 2 * PD)];
    xf[idx] = v + p;
}

// ---------------- layernorm, warp-per-row (8 rows / 256-thr block), fp16 out ----------------
__global__ void layernorm_kernel(const float* __restrict__ x,
                                 const float* __restrict__ g,
                                 const float* __restrict__ b,
                                 __half* __restrict__ yh) {
    int warp = threadIdx.x >> 5, lane = threadIdx.x & 31;
    long row = (long)blockIdx.x * 8 + warp;
    const float* xr = x + row * CC;
    float v[18];
    float s = 0.f;
    #pragma unroll
    for (int i = 0; i < 18; i++) { v[i] = xr[lane + i * 32]; s += v[i]; }
    #pragma unroll
    for (int o = 16; o; o >>= 1) s += __shfl_xor_sync(0xffffffffu, s, o);
    float mu = s * (1.0f / CC);
    float s2 = 0.f;
    #pragma unroll
    for (int i = 0; i < 18; i++) { float d = v[i] - mu; s2 += d * d; }
    #pragma unroll
    for (int o = 16; o; o >>= 1) s2 += __shfl_xor_sync(0xffffffffu, s2, o);
    float mult = 1e-5f + rsqrtf(s2 * (1.0f / CC));
    #pragma unroll
    for (int i = 0; i < 18; i++) {
        int c = lane + i * 32;
        yh[row * CC + c] = __float2half_rn((v[i] - mu) * mult * g[c] + b[c]);
    }
}

// ---------------- ALL weight transposes in one launch ----------------
#define TPL 3888
__global__ void wtrans_all_kernel(const float* __restrict__ wq, const float* __restrict__ wk,
                                  const float* __restrict__ wv, const float* __restrict__ wo,
                                  const float* __restrict__ w1, const float* __restrict__ w2,
                                  __half* __restrict__ qkTh, __half* __restrict__ qkTl,
                                  __half* __restrict__ fwh) {
    __shared__ float t[32][33];
    int bid = blockIdx.x;
    int layer = bid / TPL;
    int r = bid % TPL;
    const float* W; __half* Th; __half* Tl = nullptr;
    int Kd, Nd, n0, k0;
    if (r < 1296) {
        int widx = r / 324, tt = r % 324;
        Kd = CC; Nd = CC;
        n0 = (tt % 18) * 32; k0 = (tt / 18) * 32;
        const float* srcs0 = (widx == 0) ? wq : (widx == 1) ? wk : (widx == 2) ? wv : wo;
        W = srcs0 + (long)layer * CC * CC;
        if (widx < 2) {
            Th = qkTh + (long)layer * WLAYER + (long)widx * CC * CC;
            Tl = qkTl + (long)layer * WLAYER + (long)widx * CC * CC;
        } else if (widx == 2) {
            Th = fwh + (long)layer * W2LAYER + WV2_OFF;
        } else {
            Th = fwh + (long)layer * W2LAYER + WO2_OFF;
        }
    } else if (r < 2592) {
        int tt = r - 1296;
        Kd = CC; Nd = FF;
        n0 = (tt % 72) * 32; k0 = (tt / 72) * 32;
        W = w1 + (long)layer * CC * FF;
        Th = fwh + (long)layer * W2LAYER + W12_OFF;
    } else {
        int tt = r - 2592;
        Kd = FF; Nd = CC;
        n0 = (tt % 18) * 32; k0 = (tt / 18) * 32;
        W = w2 + (long)layer * CC * FF;
        Th = fwh + (long)layer * W2LAYER + W22_OFF;
    }
    int tx = threadIdx.x, ty = threadIdx.y;   // 32 x 8
    #pragma unroll
    for (int rr = 0; rr < 32; rr += 8)
        t[ty + rr][tx] = W[(long)(k0 + ty + rr) * Nd + (n0 + tx)];
    __syncthreads();
    #pragma unroll
    for (int rr = 0; rr < 32; rr += 8) {
        int nn = n0 + ty + rr, kk = k0 + tx;
        float xv = t[tx][ty + rr];
        __half h = __float2half_rn(xv);
        Th[(long)nn * Kd + kk] = h;
        if (Tl) Tl[(long)nn * Kd + kk] = __float2half_rn(xv - __half2float(h));
    }
}

// =================== fused flash attention v7 ===================
// grid (4, BB*NH): CTA pi handles q-tiles (7-pi) then (pi) -> uniform 9 KV-units/CTA.
// S = qh @ kh^T (1-term fp16), base-2 logits; P via ex2.approx.f16x2.
// V fp16 + ones column at dim 72 -> denominator from PV MMA. 3-stage KV ring.
#define FQCH 8192u           // 128 rows x 64B chunk
#define FQB  24576u          // 3 chunks
#define FSTG (2u*FQB)        // 49152: KH VH
#define KVSTG 3
#define FSM  (FQB + KVSTG*FSTG)   // 172032

__global__ void __launch_bounds__(256, 1)
flash_kernel(const __half* __restrict__ qkh,
             const __half* __restrict__ vf,
             const unsigned short* __restrict__ onesv,
             __half* __restrict__ af, float scale2) {   // scale2 = scale * log2(e)
    extern __shared__ char smem[];
    uint32_t sb = smem_u32(smem);
    int tid = threadIdx.x, lane = tid & 31, wid = tid >> 5;
    int z = blockIdx.y, zb = z / NH, zh = z % NH;

    const __half* khb = qkh + (long)(zb * SS) * QKN + CC + zh * DK;
    const __half* vhb = vf + (long)(zb * SS) * CC + zh * DK;

    auto load_kv = [&](int jt) {
        uint32_t st = sb + FQB + (uint32_t)(jt % KVSTG) * FSTG;
        int kbase = jt * 128;
        for (int idx = tid; idx < 1536; idx += 256) {
            int row = idx / 12, rem = idx % 12;
            int c = rem >> 2, g = rem & 3;
            int d0 = c * 32 + g * 8;
            int sz = (d0 + 8 <= DK) ? 16 : 0;
            uint32_t doff = (uint32_t)c * FQCH + swz64((uint32_t)row * 64u + (uint32_t)g * 16u);
            cpasync16(st + doff, khb + (long)(kbase + row) * QKN + d0, sz);
            if (d0 == 72)
                cpasync16(st + FQB + doff, onesv, 16);   // ones column for row-sum
            else
                cpasync16(st + FQB + doff, vhb + (long)(kbase + row) * CC + d0, sz);
        }
    };

    const int lr = lane & 15, lcq = lane >> 4;
    const float NEGINF = __int_as_float(0xff800000);

    #pragma unroll 1
    for (int half = 0; half < 2; half++) {
        int mi = half == 0 ? (7 - (int)blockIdx.x) : (int)blockIdx.x;   // heavy tile first
        int m0 = mi * 128;
        const __half* qhb = qkh + (long)(zb * SS + m0) * QKN + zh * DK;

        // ---- load Q (once per tile) ----
        for (int idx = tid; idx < 128 * 12; idx += 256) {
            int row = idx / 12, rem = idx % 12;
            int c = rem >> 2, g = rem & 3;
            int d0 = c * 32 + g * 8;
            int sz = (d0 + 8 <= DK) ? 16 : 0;
            uint32_t doff = (uint32_t)c * FQCH + swz64((uint32_t)row * 64u + (uint32_t)g * 16u);
            cpasync16(sb + doff, qhb + (long)row * QKN + d0, sz);
        }
        load_kv(0);
        CP_COMMIT();

        float oacc[10][4] = {};
        float rm0 = NEGINF, rm1 = NEGINF;
        int qrow0 = m0 + wid * 16 + (lane >> 2);
        int qrow1 = qrow0 + 8;

        for (int jt = 0; jt <= mi; jt++) {
            if (jt < mi) { load_kv(jt + 1); CP_COMMIT(); CP_WAIT(1); }
            else CP_WAIT(0);
            __syncthreads();

            uint32_t kst = sb + FQB + (uint32_t)(jt % KVSTG) * FSTG;
            uint32_t vst = kst + FQB;

            // ---- S = qh @ kh^T (1-term fp16) ----
            float sacc[16][4] = {};
            #pragma unroll
            for (int c = 0; c < 3; c++) {
                #pragma unroll
                for (int ks = 0; ks < 2; ks++) {
                    if (c == 2 && ks == 1) continue;   // dims 80..95 all zero
                    uint32_t aoff = (uint32_t)c * FQCH
                        + swz64((uint32_t)(wid*16 + lr) * 64u + (uint32_t)(ks*32 + lcq*16));
                    uint32_t qh[4];
                    ldsm4(qh, sb + aoff);
                    #pragma unroll
                    for (int np = 0; np < 8; np++) {
                        uint32_t boff = (uint32_t)c * FQCH
                            + swz64((uint32_t)(np*16 + lr) * 64u + (uint32_t)(ks*32 + lcq*16));
                        uint32_t th[4];
                        ldsm4(th, kst + boff);
                        mma16816(sacc[2*np],   qh, th[0], th[2]);
                        mma16816(sacc[2*np+1], qh, th[1], th[3]);
                    }
                }
            }

            // ---- base-2 scale + causal mask + online softmax ----
            bool diag = (jt == mi);
            int kb = jt * 128 + (lane & 3) * 2;
            float tm0 = NEGINF, tm1 = NEGINF;
            #pragma unroll
            for (int nt = 0; nt < 16; nt++) {
                int k0 = kb + nt * 8, k1 = k0 + 1;
                float s00 = sacc[nt][0] * scale2, s01 = sacc[nt][1] * scale2;
                float s10 = sacc[nt][2] * scale2, s11 = sacc[nt][3] * scale2;
                if (diag) {
                    if (k0 > qrow0) s00 = NEGINF;
                    if (k1 > qrow0) s01 = NEGINF;
                    if (k0 > qrow1) s10 = NEGINF;
                    if (k1 > qrow1) s11 = NEGINF;
                }
                sacc[nt][0] = s00; sacc[nt][1] = s01; sacc[nt][2] = s10; sacc[nt][3] = s11;
                tm0 = fmaxf(tm0, fmaxf(s00, s01));
                tm1 = fmaxf(tm1, fmaxf(s10, s11));
            }
            tm0 = fmaxf(tm0, __shfl_xor_sync(0xffffffffu, tm0, 1));
            tm0 = fmaxf(tm0, __shfl_xor_sync(0xffffffffu, tm0, 2));
            tm1 = fmaxf(tm1, __shfl_xor_sync(0xffffffffu, tm1, 1));
            tm1 = fmaxf(tm1, __shfl_xor_sync(0xffffffffu, tm1, 2));
            float nm0 = fmaxf(rm0, tm0), nm1 = fmaxf(rm1, tm1);
            float cor0 = ex2f(rm0 - nm0), cor1 = ex2f(rm1 - nm1);
            rm0 = nm0; rm1 = nm1;

            uint32_t ph[16][2];
            #pragma unroll
            for (int nt = 0; nt < 16; nt++) {
                ph[nt][0] = ex2h2(sacc[nt][0] - nm0, sacc[nt][1] - nm0);
                ph[nt][1] = ex2h2(sacc[nt][2] - nm1, sacc[nt][3] - nm1);
            }
            #pragma unroll
            for (int nt = 0; nt < 10; nt++) {
                oacc[nt][0] *= cor0; oacc[nt][1] *= cor0;
                oacc[nt][2] *= cor1; oacc[nt][3] *= cor1;
            }

            // ---- O += P @ V (fp16; col 72 = ones -> row sum) ----
            #pragma unroll
            for (int kc = 0; kc < 8; kc++) {
                uint32_t pa[4] = { ph[2*kc][0], ph[2*kc][1], ph[2*kc+1][0], ph[2*kc+1][1] };
                #pragma unroll
                for (int dg = 0; dg < 5; dg++) {
                    uint32_t addr = vst + (uint32_t)(dg >> 1) * FQCH
                        + swz64((uint32_t)(kc*16 + lr) * 64u
                                + (uint32_t)((dg & 1) * 32 + lcq * 16));
                    uint32_t t[4];
                    ldsm4t(t, addr);
                    mma16816(oacc[2*dg], pa, t[0], t[1]);
                    mma16816(oacc[2*dg+1], pa, t[2], t[3]);
                }
            }
        }
        __syncthreads();

        // ---- finalize: denominator from ones column ----
        int qbase = lane & ~3;
        float rl0 = __shfl_sync(0xffffffffu, oacc[9][0], qbase);
        float rl1 = __shfl_sync(0xffffffffu, oacc[9][2], qbase);
        float inv0 = 1.0f / rl0, inv1 = 1.0f / rl1;
        long base0 = (long)(zb * SS + qrow0) * CC + zh * DK;
        int c0 = (lane & 3) * 2;
        #pragma unroll
        for (int nt = 0; nt < 9; nt++) {
            int d = nt * 8 + c0;
            *(__half2*)&af[base0 + d] =
                __floats2half2_rn(oacc[nt][0] * inv0, oacc[nt][1] * inv0);
            *(__half2*)&af[base0 + 8 * CC + d] =
                __floats2half2_rn(oacc[nt][2] * inv1, oacc[nt][3] * inv1);
        }
    }
}

// =================== HMMA GEMM (templated row width BKT = 32 or 64) ===================
// EPI: 3 +bias+resid fp32 out, 4 plain fp16 out, 6 +bias+GeLU2 fp16 out
template<int EPI, bool B2, int NT, int BKT>
__global__ void __launch_bounds__(256, 1)
hmma_gemm(const uint16_t* __restrict__ Ah, int lda,
          const uint16_t* __restrict__ Bh, const uint16_t* __restrict__ Bl, int ldb,
          float* __restrict__ C, __half* __restrict__ Ch,
          int ldc,
          const float* __restrict__ bias, const float* __restrict__ resid,
          int M, int N, int K) {
    constexpr int BN = 32 * NT;
    constexpr int RB = BKT * 2;                // bytes per row
    constexpr int G  = RB / 16;                // 16B groups per row
    constexpr int KS = BKT / 16;               // k-steps per chunk
    constexpr uint32_t OPA = (uint32_t)BM * RB;
    constexpr uint32_t OPB = (uint32_t)BN * RB;
    constexpr uint32_t OFF_BH = OPA;
    constexpr uint32_t OFF_BL = OFF_BH + OPB;
    constexpr uint32_t STAGE = OFF_BH + OPB * (B2 ? 2 : 1);

    auto swz = [](uint32_t o) -> uint32_t {
        return (RB == 64) ? (o ^ ((o >> 3) & 0x30)) : (o ^ ((o >> 3) & 0x70));
    };

    int m0 = blockIdx.y * BM, n0 = blockIdx.x * BN;

    extern __shared__ char smem[];
    uint32_t sb = smem_u32(smem);
    int tid = threadIdx.x;

    int nch = (K + BKT - 1) / BKT;

    auto fill = [&](int chunk) {
        int k0 = chunk * BKT;
        uint32_t sbase = sb + (uint32_t)(chunk % STAGES) * STAGE;
        const int ATOT = BM * G, BTOT = BN * G;
        for (int idx = tid; idx < ATOT + BTOT; idx += 256) {
            if (idx < ATOT) {
                int row = idx / G, gr = idx % G;
                int kk = k0 + gr * 8;
                int ksz = (kk + 8 <= K) ? 16 : 0;
                uint32_t doff = swz((uint32_t)row * RB + (uint32_t)gr * 16u);
                long aoff = (long)(m0 + row) * lda + kk;
                cpasync16(sbase + doff, Ah + aoff, ksz);
            } else {
                int j = idx - ATOT;
                int row = j / G, gr = j % G;
                int kk = k0 + gr * 8;
                int nn = n0 + row;
                int bsz = (nn < N && kk + 8 <= K) ? 16 : 0;
                long boff = (long)min(nn, N - 1) * ldb + kk;
                uint32_t doff = swz((uint32_t)row * RB + (uint32_t)gr * 16u);
                cpasync16(sbase + OFF_BH + doff, Bh + boff, bsz);
                if (B2) cpasync16(sbase + OFF_BL + doff, Bl + boff, bsz);
            }
        }
    };

    fill(0); CP_COMMIT();
    if (nch > 1) fill(1);
    CP_COMMIT();

    int lane = tid & 31, wid = tid >> 5;
    int wm = wid & 1, wn = wid >> 1;
    int lr = lane & 15, lc = lane >> 4;

    float acc[4][NT][4] = {};

    for (int c = 0; c < nch; c++) {
        if (c + 2 < nch) fill(c + 2);
        CP_COMMIT();
        CP_WAIT(2);
        __syncthreads();
        uint32_t sbase = sb + (uint32_t)(c % STAGES) * STAGE;
        #pragma unroll
        for (int ks = 0; ks < KS; ks++) {
            uint32_t ah[4][4], bh[NT][2], bl[NT][2];
            #pragma unroll
            for (int mt = 0; mt < 4; mt++) {
                uint32_t off = swz((uint32_t)(wm*64 + mt*16 + lr) * RB
                                   + (uint32_t)(ks*32 + lc*16));
                ldsm4(ah[mt], sbase + off);
            }
            #pragma unroll
            for (int np = 0; np < NT/2; np++) {
                uint32_t off = swz((uint32_t)(wn*(8*NT) + np*16 + lr) * RB
                                   + (uint32_t)(ks*32 + lc*16));
                uint32_t t[4];
                ldsm4(t, sbase + OFF_BH + off);
                bh[2*np][0] = t[0]; bh[2*np+1][0] = t[1];
                bh[2*np][1] = t[2]; bh[2*np+1][1] = t[3];
                if (B2) {
                    ldsm4(t, sbase + OFF_BL + off);
                    bl[2*np][0] = t[0]; bl[2*np+1][0] = t[1];
                    bl[2*np][1] = t[2]; bl[2*np+1][1] = t[3];
                }
            }
            #pragma unroll
            for (int mt = 0; mt < 4; mt++)
                #pragma unroll
                for (int nt = 0; nt < NT; nt++) {
                    mma16816(acc[mt][nt], ah[mt], bh[nt][0], bh[nt][1]);
                    if (B2) mma16816(acc[mt][nt], ah[mt], bl[nt][0], bl[nt][1]);
                }
        }
        __syncthreads();
    }

    int r0 = lane >> 2, c0 = (lane & 3) * 2;
    #pragma unroll
    for (int mt = 0; mt < 4; mt++) {
        #pragma unroll
        for (int nt = 0; nt < NT; nt++) {
            int gn = n0 + wn*(8*NT) + nt*8 + c0;
            if (gn >= N) continue;
            int gmb = m0 + wm*64 + mt*16 + r0;
            float* ac = acc[mt][nt];
            #pragma unroll
            for (int h2 = 0; h2 < 2; h2++) {
                int gm = gmb + h2 * 8;
                float v0 = ac[h2*2 + 0];
                float v1 = ac[h2*2 + 1];
                long off = (long)gm * ldc + gn;
                if (EPI == 3) {
                    float2 r = *(const float2*)&resid[off];
                    v0 += bias[gn] + r.x;
                    v1 += bias[gn + 1] + r.y;
                    *(float2*)&C[off] = make_float2(v0, v1);
                } else if (EPI == 4) {
                    __half2 o2;
                    o2.x = __float2half_rn(v0);
                    o2.y = __float2half_rn(v1);
                    *(__half2*)&Ch[off] = o2;
                } else if (EPI == 6) {
                    v0 += bias[gn]; v1 += bias[gn + 1];
                    v0 = v0 / (1.f + __expf(-1.702f * v0));
                    v1 = v1 / (1.f + __expf(-1.702f * v1));
                    __half2 o2;
                    o2.x = __float2half_rn(v0);
                    o2.y = __float2half_rn(v1);
                    *(__half2*)&((__half*)C)[off] = o2;
                }
            }
        }
    }
}

#define SM_QK       73728   // 3*(8192 + 2*8192)     BK32 B2 NT4
#define SM_B64_NT4  98304   // 3*(16384 + 16384)     BK64 B1 NT4
#define SM_B64_NT2  73728   // 3*(16384 + 8192)      BK64 B1 NT2

// ---------------- host orchestration ----------------
extern "C" void kernel_launch(void* const* d_in, const int* in_sizes, int n_in,
                              void* d_out, int out_size) {
    (void)in_sizes; (void)n_in; (void)out_size;
    const float* x     = (const float*)d_in[0];
    const float* pos0  = (const float*)d_in[1];
    const float* pos1  = (const float*)d_in[2];
    const float* pos2  = (const float*)d_in[3];
    const float* ln1_g = (const float*)d_in[4];
    const float* ln1_b = (const float*)d_in[5];
    const float* wq    = (const float*)d_in[6];
    const float* wk    = (const float*)d_in[7];
    const float* wv    = (const float*)d_in[8];
    const float* wo    = (const float*)d_in[9];
    const float* wo_b  = (const float*)d_in[10];
    const float* ln2_g = (const float*)d_in[11];
    const float* ln2_b = (const float*)d_in[12];
    const float* w1    = (const float*)d_in[13];
    const float* b1    = (const float*)d_in[14];
    const float* w2    = (const float*)d_in[15];
    const float* b2    = (const float*)d_in[16];

    float *xf;
    __half *hh,*qkh,*vf,*af,*ffn,*wth,*wtl,*fwh;
    unsigned short* onesv;
    cudaGetSymbolAddress((void**)&xf,   g_xf);
    cudaGetSymbolAddress((void**)&hh,   g_hh);
    cudaGetSymbolAddress((void**)&qkh,  g_qkh);
    cudaGetSymbolAddress((void**)&vf,   g_vf);
    cudaGetSymbolAddress((void**)&af,   g_af);
    cudaGetSymbolAddress((void**)&ffn,  g_ffn);
    cudaGetSymbolAddress((void**)&wth,  g_wth);  cudaGetSymbolAddress((void**)&wtl,  g_wtl);
    cudaGetSymbolAddress((void**)&fwh,  g_fwh);
    cudaGetSymbolAddress((void**)&onesv, g_ones);

    auto kQK    = hmma_gemm<4,true ,4,32>;   // fp16 out, 2-term weights, BK32
    auto kV     = hmma_gemm<4,false,4,64>;   // fp16 out, BK64
    auto kWO    = hmma_gemm<3,false,2,64>;   // fp32 +bias+resid, BK64
    auto kFFN1  = hmma_gemm<6,false,4,64>;   // fp16 +bias+gelu, BK64
    auto kFFN2  = hmma_gemm<3,false,2,64>;   // fp32 +bias+resid, BK64

    cudaFuncSetAttribute(kQK,   cudaFuncAttributeMaxDynamicSharedMemorySize, SM_QK);
    cudaFuncSetAttribute(kV,    cudaFuncAttributeMaxDynamicSharedMemorySize, SM_B64_NT4);
    cudaFuncSetAttribute(kWO,   cudaFuncAttributeMaxDynamicSharedMemorySize, SM_B64_NT2);
    cudaFuncSetAttribute(kFFN1, cudaFuncAttributeMaxDynamicSharedMemorySize, SM_B64_NT4);
    cudaFuncSetAttribute(kFFN2, cudaFuncAttributeMaxDynamicSharedMemorySize, SM_B64_NT2);
    cudaFuncSetAttribute(flash_kernel, cudaFuncAttributeMaxDynamicSharedMemorySize, FSM);

    const float scale2 = (1.0f / sqrtf((float)DK)) * 1.4426950408889634f;
    long n_elem = (long)MM * CC;
    int nb = (int)((n_elem + 255) / 256);

    shiftpos_kernel<<<nb, 256>>>(x, pos0, pos1, pos2, xf);
    wtrans_all_kernel<<<LL * TPL, dim3(32, 8)>>>(wq, wk, wv, wo, w1, w2, wth, wtl, fwh);

    dim3 gQK(QKN/128, MM/BM, 1);               // (9, 32) — 288 CTAs
    dim3 gV((CC + 127)/128, MM/BM, 1);         // (5, 32)
    dim3 gFlash(4, BB*NH);                     // (4, 32) — 128 CTAs, balanced pairs
    dim3 gN2(CC/64, MM/BM, 1);                 // (9, 32)
    dim3 gF1(FF/128, MM/BM, 1);                // (18, 32)

    for (int l = 0; l < LL; l++) {
        long wb = (long)l * WLAYER;
        long fb = (long)l * W2LAYER;
        // --- attention ---
        layernorm_kernel<<<MM/8, 256>>>(xf, ln1_g + l*CC, ln1_b + l*CC, hh);
        kQK<<<gQK, 256, SM_QK>>>(
            (const uint16_t*)hh, CC,
            (const uint16_t*)(wth + wb), (const uint16_t*)(wtl + wb), CC,
            nullptr, qkh, QKN, nullptr, nullptr, MM, QKN, CC);
        kV<<<gV, 256, SM_B64_NT4>>>(
            (const uint16_t*)hh, CC,
            (const uint16_t*)(fwh + fb + WV2_OFF), nullptr, CC,
            nullptr, vf, CC, nullptr, nullptr, MM, CC, CC);
        flash_kernel<<<gFlash, 256, FSM>>>(qkh, vf, onesv, af, scale2);
        kWO<<<gN2, 256, SM_B64_NT2>>>(
            (const uint16_t*)af, CC,
            (const uint16_t*)(fwh + fb + WO2_OFF), nullptr, CC,
            xf, nullptr, CC, wo_b + l*CC, xf, MM, CC, CC);

        // --- FFN ---
        layernorm_kernel<<<MM/8, 256>>>(xf, ln2_g + l*CC, ln2_b + l*CC, hh);
        kFFN1<<<gF1, 256, SM_B64_NT4>>>(
            (const uint16_t*)hh, CC,
            (const uint16_t*)(fwh + fb + W12_OFF), nullptr, CC,
            (float*)ffn, nullptr, FF, b1 + (long)l*FF, nullptr, MM, FF, CC);
        float* outp = (l == LL - 1) ? (float*)d_out : xf;
        kFFN2<<<gN2, 256, SM_B64_NT2>>>(
            (const uint16_t*)ffn, FF,
            (const uint16_t*)(fwh + fb + W22_OFF), nullptr, FF,
            outp, nullptr, CC, b2 + (long)l*CC, xf, MM, CC, FF);
    }
}